// round 7
// baseline (speedup 1.0000x reference)
#include <cuda_runtime.h>
#include <cuda_bf16.h>

// Rejection sampler for speculative decoding — single fused kernel, v2.
//
// Inputs indexed from the END of d_in:
//   d_in[0]        draft_token_ids  int32 [N]
//   d_in[n_in-5]   draft_probs      f32   [N,V]
//   d_in[n_in-4]   target_probs     f32   [N,V]
//   d_in[n_in-3]   bonus_token_ids  int32 [B,1]
//   d_in[n_in-2]   uniform_samples  f32   [N]
//   d_in[n_in-1]   uniform_recover  f32   [N]
// Output FLOAT32: out[B,K+1], num_accepted[B], accepted[B], recovered[B], bonus[B].
//
// v2: phase 1 is a PURE streaming loop — each warp owns one contiguous
// 1/16th of the row and accumulates adj-sum and t-sum in two registers
// (no shuffles / SMEM traffic inside the load loop; one warp reduction
// total). Phase 2 scans the 16 warp-chunk sums, finds the CDF crossing
// chunk, and re-resolves it from L2-hot data with an ordered descent.

#define EPS 1e-10f
#define THREADS 512
#define NWARP (THREADS / 32)
#define FULLM 0xFFFFFFFFu

__device__ int g_accept[8192];
__device__ int g_rec[8192];
__device__ int g_done = 0;

__global__ void __launch_bounds__(THREADS)
fused_kernel(const int* __restrict__ tok,
             const float* __restrict__ dp,
             const float* __restrict__ tp,
             const int* __restrict__ bonus,
             const float* __restrict__ u_samp,
             const float* __restrict__ u_rec,
             float* __restrict__ out,
             int V, int B, int K, int out_size)
{
    __shared__ float s_seg_adj[NWARP];
    __shared__ float s_seg_t[NWARP];
    __shared__ int   s_last;

    const int row  = blockIdx.x;
    const int tid  = threadIdx.x;
    const int lane = tid & 31;
    const int wid  = tid >> 5;

    const float* __restrict__ d = dp + (size_t)row * V;
    const float* __restrict__ t = tp + (size_t)row * V;

    const int V4      = V >> 2;
    const int chunkF4 = (V4 + NWARP - 1) / NWARP;   // float4 per warp chunk

    const float4* __restrict__ d4 = (const float4*)d;
    const float4* __restrict__ t4 = (const float4*)t;

    // ---- Phase 1: pure streaming accumulation, one chunk per warp.
    {
        const int wbeg = wid * chunkF4;
        const int wend = min(wbeg + chunkF4, V4);
        float av = 0.f, tv = 0.f;
        #pragma unroll 4
        for (int j = wbeg + lane; j < wend; j += 32) {
            float4 a = t4[j];
            float4 b = d4[j];
            av += fmaxf(a.x - b.x, 0.f) + fmaxf(a.y - b.y, 0.f)
                + fmaxf(a.z - b.z, 0.f) + fmaxf(a.w - b.w, 0.f);
            tv += a.x + a.y + a.z + a.w;
        }
        #pragma unroll
        for (int o = 16; o > 0; o >>= 1) {
            av += __shfl_down_sync(FULLM, av, o);
            tv += __shfl_down_sync(FULLM, tv, o);
        }
        if (lane == 0) { s_seg_adj[wid] = av; s_seg_t[wid] = tv; }
    }
    __syncthreads();
    if (tid == 0 && (V & 3)) {                    // scalar tail -> last chunk
        float a_add = 0.f, t_add = 0.f;
        for (int e = V4 << 2; e < V; e++) {
            float tv2 = t[e], dv2 = d[e];
            a_add += fmaxf(tv2 - dv2, 0.f);
            t_add += tv2;
        }
        s_seg_adj[NWARP - 1] += a_add;
        s_seg_t[NWARP - 1]   += t_add;
    }
    __syncthreads();

    // ---- Acceptance test (warp 1, overlaps warp 0's phase 2).
    if (tid == 32) {
        int tk = tok[row];
        float pd = d[tk];
        float pt = t[tk];
        g_accept[row] = (u_samp[row] < fminf(1.f, pt / fmaxf(pd, EPS))) ? 1 : 0;
    }

    // ---- Phase 2 (warp 0): scan chunk sums, locate crossing, resolve.
    if (wid == 0) {
        const float u = u_rec[row];

        // inclusive scan of the 16 adj chunk sums across lanes
        float segv = (lane < NWARP) ? s_seg_adj[lane] : 0.f;
        float inc = segv;
        #pragma unroll
        for (int o = 1; o < 32; o <<= 1) {
            float nb = __shfl_up_sync(FULLM, inc, o);
            if (lane >= o) inc += nb;
        }
        float stot = __shfl_sync(FULLM, inc, 31);

        const bool fb = !(stot > EPS);            // fallback: sample target_probs
        float T;
        if (fb) {
            segv = (lane < NWARP) ? s_seg_t[lane] : 0.f;
            inc = segv;
            #pragma unroll
            for (int o = 1; o < 32; o <<= 1) {
                float nb = __shfl_up_sync(FULLM, inc, o);
                if (lane >= o) inc += nb;
            }
            T = u;                                // target already normalized
        } else {
            T = u * stot;                         // cumsum/s < u <=> cumsum < u*s
        }
        float excl = inc - segv;

        // first chunk whose inclusive prefix reaches T
        unsigned m = __ballot_sync(FULLM, (lane < NWARP) && (inc >= T));
        int sidx = m ? (__ffs(m) - 1) : -1;

        int count;
        if (sidx < 0) {
            count = V;
        } else {
            float pb = __shfl_sync(FULLM, excl, sidx);
            const int segbeg = sidx * chunkF4;
            const int segend = min(segbeg + chunkF4, V4);

            float base = pb;
            int   cnt  = 0;
            for (int j0 = segbeg; j0 < segend; j0 += 32) {
                int j = j0 + lane;
                float e0 = 0.f, e1 = 0.f, e2 = 0.f, e3 = 0.f;
                if (j < segend) {
                    float4 a = t4[j];
                    if (fb) {
                        e0 = a.x; e1 = a.y; e2 = a.z; e3 = a.w;
                    } else {
                        float4 b = d4[j];
                        e0 = fmaxf(a.x - b.x, 0.f);
                        e1 = fmaxf(a.y - b.y, 0.f);
                        e2 = fmaxf(a.z - b.z, 0.f);
                        e3 = fmaxf(a.w - b.w, 0.f);
                    }
                }
                float p0 = e0, p1 = p0 + e1, p2 = p1 + e2, p3 = p2 + e3;
                float ls = p3;
                float inc2 = ls;
                #pragma unroll
                for (int o = 1; o < 32; o <<= 1) {
                    float nb = __shfl_up_sync(FULLM, inc2, o);
                    if (lane >= o) inc2 += nb;
                }
                float subtotal = __shfl_sync(FULLM, inc2, 31);
                float bofs = base + (inc2 - ls);
                if (j < segend) {
                    cnt += (bofs + p0 < T) ? 1 : 0;
                    cnt += (bofs + p1 < T) ? 1 : 0;
                    cnt += (bofs + p2 < T) ? 1 : 0;
                    cnt += (bofs + p3 < T) ? 1 : 0;
                }
                base += subtotal;
            }
            // Scalar tail (V not multiple of 4; unreachable for V=32000).
            if (sidx == NWARP - 1 && (V & 3)) {
                int tcnt = 0;
                if (lane == 0) {
                    float run = base;
                    for (int e = V4 << 2; e < V; e++) {
                        run += fb ? t[e] : fmaxf(t[e] - d[e], 0.f);
                        tcnt += (run < T) ? 1 : 0;
                    }
                }
                cnt += __shfl_sync(FULLM, tcnt, 0) ? (lane == 0 ? 0 : 0) : 0;
                if (lane == 0) cnt += tcnt;
            }
            #pragma unroll
            for (int o = 16; o > 0; o >>= 1)
                cnt += __shfl_down_sync(FULLM, cnt, o);
            count = (segbeg << 2) + cnt;
        }
        if (lane == 0) g_rec[row] = min(count, V - 1);
    }

    // ---- Last-CTA finalize.
    __syncthreads();
    if (tid == 0) {
        __threadfence();
        int ticket = atomicAdd(&g_done, 1);
        s_last = (ticket == (int)gridDim.x - 1) ? 1 : 0;
        if (s_last) {
            g_done = 0;
            __threadfence();
        }
    }
    __syncthreads();
    if (s_last) {
        for (int b = tid; b < B; b += THREADS) {
            int n_acc = 0;
            for (int i = 0; i < K; i++) {
                if (g_accept[b * K + i]) n_acc++;
                else break;
            }
            bool all_acc = (n_acc == K);
            int rec_at = g_rec[b * K + min(n_acc, K - 1)];
            int fin = all_acc ? bonus[b] : rec_at;

            float* o = out + b * (K + 1);
            for (int i = 0; i <= K; i++)
                o[i] = (i < n_acc) ? (float)tok[b * K + i] : -1.0f;
            o[n_acc] = (float)fin;

            int base = B * (K + 1);
            if (base + 4 * B <= out_size) {
                out[base + b]         = (float)(n_acc + 1);
                out[base + B + b]     = (float)n_acc;
                out[base + 2 * B + b] = all_acc ? 0.0f : 1.0f;
                out[base + 3 * B + b] = all_acc ? 1.0f : 0.0f;
            }
        }
    }
}

extern "C" void kernel_launch(void* const* d_in, const int* in_sizes, int n_in,
                              void* d_out, int out_size)
{
    const int*   tok   = (const int*)d_in[0];
    const float* dp    = (const float*)d_in[n_in - 5];
    const float* tp    = (const float*)d_in[n_in - 4];
    const int*   bonus = (const int*)d_in[n_in - 3];
    const float* us    = (const float*)d_in[n_in - 2];
    const float* ur    = (const float*)d_in[n_in - 1];
    float*       out   = (float*)d_out;

    const int N = in_sizes[0];
    const int B = in_sizes[n_in - 3];
    const int V = in_sizes[n_in - 4] / N;
    const int K = N / B;

    fused_kernel<<<N, THREADS>>>(tok, dp, tp, bonus, us, ur, out,
                                 V, B, K, out_size);
}

// round 8
// speedup vs baseline: 1.3583x; 1.3583x over previous
#include <cuda_runtime.h>
#include <cuda_bf16.h>

// Rejection sampler for speculative decoding — single fused kernel, v3.
//
// Inputs indexed from the END of d_in:
//   d_in[0]        draft_token_ids  int32 [N]
//   d_in[n_in-5]   draft_probs      f32   [N,V]
//   d_in[n_in-4]   target_probs     f32   [N,V]
//   d_in[n_in-3]   bonus_token_ids  int32 [B,1]
//   d_in[n_in-2]   uniform_samples  f32   [N]
//   d_in[n_in-1]   uniform_recover  f32   [N]
// Output FLOAT32: out[B,K+1], num_accepted[B], accepted[B], recovered[B], bonus[B].
//
// v3: CTA-wide strided streaming (the access pattern that measured DRAM=65.6%)
// but the per-iteration warp shuffle reduction is replaced by a dependency-free
// STS of each thread's 4-element adj sum into a padded SMEM part array
// (8192 parts, 34 KB). Phase 2 resolves the inverse-CDF crossing entirely from
// SMEM in 3 ballot levels + one L2-hot float4 re-read.

#define EPS     1e-10f
#define THREADS 512
#define NWARP   (THREADS / 32)
#define FULLM   0xFFFFFFFFu
#define PARTCAP 8192                   // float4-granularity parts; V <= 32768
#define PARTPAD (PARTCAP + PARTCAP / 16)

__device__ int g_accept[8192];
__device__ int g_rec[8192];
__device__ int g_done = 0;

__device__ __forceinline__ int pf(int j) { return j + (j >> 4); }  // pad index

__device__ __forceinline__ float warp_incl_scan(float v, int lane) {
    #pragma unroll
    for (int o = 1; o < 32; o <<= 1) {
        float nb = __shfl_up_sync(FULLM, v, o);
        if (lane >= o) v += nb;
    }
    return v;
}

__global__ void __launch_bounds__(THREADS)
fused_kernel(const int* __restrict__ tok,
             const float* __restrict__ dp,
             const float* __restrict__ tp,
             const int* __restrict__ bonus,
             const float* __restrict__ u_samp,
             const float* __restrict__ u_rec,
             float* __restrict__ out,
             int V, int B, int K, int out_size)
{
    __shared__ float s_part[PARTPAD];
    __shared__ float s_seg[NWARP];
    __shared__ float s_tail[2];        // [0]=tail adj sum, [1]=tail t sum
    __shared__ int   s_last;

    const int row  = blockIdx.x;
    const int tid  = threadIdx.x;
    const int lane = tid & 31;
    const int wid  = tid >> 5;

    const float* __restrict__ d = dp + (size_t)row * V;
    const float* __restrict__ t = tp + (size_t)row * V;

    const int V4     = V >> 2;
    const int n_iter = (V4 + THREADS - 1) / THREADS;

    const float4* __restrict__ d4 = (const float4*)d;
    const float4* __restrict__ t4 = (const float4*)t;

    // ---- Phase 1: CTA-wide strided stream; dependency-free STS of part sums.
    for (int i = 0; i < n_iter; i++) {
        int j = i * THREADS + tid;
        float av = 0.f;
        if (j < V4) {
            float4 a = t4[j];
            float4 b = d4[j];
            av = fmaxf(a.x - b.x, 0.f) + fmaxf(a.y - b.y, 0.f)
               + fmaxf(a.z - b.z, 0.f) + fmaxf(a.w - b.w, 0.f);
        }
        if (j < PARTCAP) s_part[pf(j)] = av;
    }
    for (int p = n_iter * THREADS + tid; p < PARTCAP; p += THREADS)
        s_part[pf(p)] = 0.f;

    if (tid == 0) {
        // scalar tail (V not multiple of 4; dead for V=32000)
        float ta = 0.f, tt = 0.f;
        for (int e = V4 << 2; e < V; e++) {
            float tv = t[e], dv = d[e];
            ta += fmaxf(tv - dv, 0.f);
            tt += tv;
        }
        s_tail[0] = ta; s_tail[1] = tt;
        // acceptance test for this row
        int tk = tok[row];
        float pd = d[tk];
        float pt = t[tk];
        g_accept[row] = (u_samp[row] < fminf(1.f, pt / fmaxf(pd, EPS))) ? 1 : 0;
    }
    __syncthreads();

    // ---- Phase 2a: per-warp segment totals (each warp owns 512 parts).
    {
        int base = wid * 512 + lane * 16;
        float ls = 0.f;
        #pragma unroll
        for (int k = 0; k < 16; k++) ls += s_part[pf(base + k)];
        #pragma unroll
        for (int o = 16; o > 0; o >>= 1)
            ls += __shfl_down_sync(FULLM, ls, o);
        if (lane == 0) s_seg[wid] = ls;
    }
    __syncthreads();

    // ---- Phase 2b: warp 0 resolves the inverse-CDF crossing.
    if (wid == 0) {
        const float u = u_rec[row];

        float segv = (lane < NWARP) ? s_seg[lane] : 0.f;
        float inc  = warp_incl_scan(segv, lane);
        float ptot = __shfl_sync(FULLM, inc, NWARP - 1);
        float stot = ptot + s_tail[0];

        const bool fb = !(stot > EPS);        // fallback: sample target_probs
        float T, tail_eff;
        if (fb) {
            // Cold path: rebuild parts + segments from t (never taken for
            // well-formed inputs; correctness only).
            for (int j0 = 0; j0 < PARTCAP; j0 += 32) {
                int j = j0 + lane;
                float tvv = 0.f;
                if (j < V4) { float4 a = t4[j]; tvv = a.x + a.y + a.z + a.w; }
                s_part[pf(j)] = tvv;
            }
            __syncwarp();
            segv = 0.f;
            if (lane < NWARP)
                for (int k = 0; k < 512; k++)
                    segv += s_part[pf(lane * 512 + k)];
            inc  = warp_incl_scan(segv, lane);
            ptot = __shfl_sync(FULLM, inc, NWARP - 1);
            T = u;                            // target already normalized
            tail_eff = s_tail[1];
        } else {
            T = u * stot;                     // cumsum/s < u  <=>  cumsum < u*s
            tail_eff = s_tail[0];
        }
        (void)tail_eff;
        float excl = inc - segv;

        unsigned m = __ballot_sync(FULLM, (lane < NWARP) && (inc >= T));
        int count;
        if (m == 0) {
            // crossing beyond all parts: all 4*V4 elements < T; walk tail.
            int cc = 0;
            if (lane == 0) {
                float run = ptot;
                for (int e = V4 << 2; e < V; e++) {
                    run += fb ? t[e] : fmaxf(t[e] - d[e], 0.f);
                    cc += (run < T) ? 1 : 0;
                }
            }
            count = (V4 << 2) + __shfl_sync(FULLM, cc, 0);
        } else {
            int   ws = __ffs(m) - 1;
            float pb = __shfl_sync(FULLM, excl, ws);

            // level 2: 32 lanes x 16 parts within segment ws
            int base = ws * 512 + lane * 16;
            float ls = 0.f;
            #pragma unroll
            for (int k = 0; k < 16; k++) ls += s_part[pf(base + k)];
            float inc2 = warp_incl_scan(ls, lane);
            unsigned m2 = __ballot_sync(FULLM, pb + inc2 >= T);
            int   L  = __ffs(m2) - 1;         // guaranteed to exist
            float q  = pb + __shfl_sync(FULLM, inc2 - ls, L);

            // level 3: 16 parts of lane L distributed over lanes 0..15
            float pv = (lane < 16) ? s_part[pf(ws * 512 + L * 16 + lane)] : 0.f;
            float inc3 = warp_incl_scan(pv, lane);
            unsigned m3 = __ballot_sync(FULLM, (lane < 16) && (q + inc3 >= T));
            int   pi = __ffs(m3) - 1;         // guaranteed to exist
            int   P  = ws * 512 + L * 16 + pi;
            float r  = q + __shfl_sync(FULLM, inc3 - pv, pi);

            // level 4: resolve within the 4 elements of part P (L2-hot read)
            int cin = 0;
            if (lane == 0) {
                float4 a = t4[P];
                float e0, e1, e2, e3;
                if (fb) {
                    e0 = a.x; e1 = a.y; e2 = a.z; e3 = a.w;
                } else {
                    float4 b = d4[P];
                    e0 = fmaxf(a.x - b.x, 0.f);
                    e1 = fmaxf(a.y - b.y, 0.f);
                    e2 = fmaxf(a.z - b.z, 0.f);
                    e3 = fmaxf(a.w - b.w, 0.f);
                }
                float run = r;
                run += e0; cin += (run < T) ? 1 : 0;
                run += e1; cin += (run < T) ? 1 : 0;
                run += e2; cin += (run < T) ? 1 : 0;
                run += e3; cin += (run < T) ? 1 : 0;
            }
            count = (P << 2) + __shfl_sync(FULLM, cin, 0);
        }
        if (lane == 0) g_rec[row] = min(count, V - 1);
    }

    // ---- Last-CTA finalize.
    __syncthreads();
    if (tid == 0) {
        __threadfence();
        int ticket = atomicAdd(&g_done, 1);
        s_last = (ticket == (int)gridDim.x - 1) ? 1 : 0;
        if (s_last) {
            g_done = 0;
            __threadfence();
        }
    }
    __syncthreads();
    if (s_last) {
        for (int b = tid; b < B; b += THREADS) {
            int n_acc = 0;
            for (int i = 0; i < K; i++) {
                if (g_accept[b * K + i]) n_acc++;
                else break;
            }
            bool all_acc = (n_acc == K);
            int rec_at = g_rec[b * K + min(n_acc, K - 1)];
            int fin = all_acc ? bonus[b] : rec_at;

            float* o = out + b * (K + 1);
            for (int i = 0; i <= K; i++)
                o[i] = (i < n_acc) ? (float)tok[b * K + i] : -1.0f;
            o[n_acc] = (float)fin;

            int base = B * (K + 1);
            if (base + 4 * B <= out_size) {
                out[base + b]         = (float)(n_acc + 1);
                out[base + B + b]     = (float)n_acc;
                out[base + 2 * B + b] = all_acc ? 0.0f : 1.0f;
                out[base + 3 * B + b] = all_acc ? 1.0f : 0.0f;
            }
        }
    }
}

extern "C" void kernel_launch(void* const* d_in, const int* in_sizes, int n_in,
                              void* d_out, int out_size)
{
    const int*   tok   = (const int*)d_in[0];
    const float* dp    = (const float*)d_in[n_in - 5];
    const float* tp    = (const float*)d_in[n_in - 4];
    const int*   bonus = (const int*)d_in[n_in - 3];
    const float* us    = (const float*)d_in[n_in - 2];
    const float* ur    = (const float*)d_in[n_in - 1];
    float*       out   = (float*)d_out;

    const int N = in_sizes[0];
    const int B = in_sizes[n_in - 3];
    const int V = in_sizes[n_in - 4] / N;
    const int K = N / B;

    fused_kernel<<<N, THREADS>>>(tok, dp, tp, bonus, us, ur, out,
                                 V, B, K, out_size);
}

// round 9
// speedup vs baseline: 1.4167x; 1.0430x over previous
#include <cuda_runtime.h>
#include <cuda_bf16.h>

// Rejection sampler for speculative decoding — single fused kernel, v4.
//
// Inputs indexed from the END of d_in:
//   d_in[0]        draft_token_ids  int32 [N]
//   d_in[n_in-5]   draft_probs      f32   [N,V]
//   d_in[n_in-4]   target_probs     f32   [N,V]
//   d_in[n_in-3]   bonus_token_ids  int32 [B,1]
//   d_in[n_in-2]   uniform_samples  f32   [N]
//   d_in[n_in-1]   uniform_recover  f32   [N]
// Output FLOAT32: out[B,K+1], num_accepted[B], accepted[B], recovered[B], bonus[B].
//
// v4 = v3 skeleton with doubled per-thread MLP: each thread handles two
// consecutive float4s per iteration (4 independent streaming LDG.128 before
// any consume), parts at 8-element granularity (4000 parts, 16 KB SMEM),
// conflict-free 1-per-8 padding, 4-level ballot descent.

#define EPS     1e-10f
#define THREADS 512
#define NWARP   (THREADS / 32)
#define FULLM   0xFFFFFFFFu
#define PARTCAP 4096                   // 8-element parts; V <= 32768
#define PARTPAD (PARTCAP + PARTCAP / 8)

__device__ int g_accept[8192];
__device__ int g_rec[8192];
__device__ int g_done = 0;

__device__ __forceinline__ int pf(int p) { return p + (p >> 3); }  // pad index

__device__ __forceinline__ float warp_incl_scan(float v, int lane) {
    #pragma unroll
    for (int o = 1; o < 32; o <<= 1) {
        float nb = __shfl_up_sync(FULLM, v, o);
        if (lane >= o) v += nb;
    }
    return v;
}

__device__ __forceinline__ float maxdiff4(float4 a, float4 b) {
    return fmaxf(a.x - b.x, 0.f) + fmaxf(a.y - b.y, 0.f)
         + fmaxf(a.z - b.z, 0.f) + fmaxf(a.w - b.w, 0.f);
}

__global__ void __launch_bounds__(THREADS)
fused_kernel(const int* __restrict__ tok,
             const float* __restrict__ dp,
             const float* __restrict__ tp,
             const int* __restrict__ bonus,
             const float* __restrict__ u_samp,
             const float* __restrict__ u_rec,
             float* __restrict__ out,
             int V, int B, int K, int out_size)
{
    __shared__ float s_part[PARTPAD];
    __shared__ float s_seg[NWARP];
    __shared__ float s_tail[2];        // [0]=tail adj sum, [1]=tail t sum
    __shared__ int   s_last;

    const int row  = blockIdx.x;
    const int tid  = threadIdx.x;
    const int lane = tid & 31;
    const int wid  = tid >> 5;

    const float* __restrict__ d = dp + (size_t)row * V;
    const float* __restrict__ t = tp + (size_t)row * V;

    const int V4 = V >> 2;
    const int NP = (V4 + 1) >> 1;          // 8-element parts
    const int n_iter = (NP + THREADS - 1) / THREADS;

    const float4* __restrict__ d4 = (const float4*)d;
    const float4* __restrict__ t4 = (const float4*)t;

    // ---- Phase 1: stream; 4 independent streaming loads per thread-iter.
    for (int i = 0; i < n_iter; i++) {
        int p = i * THREADS + tid;
        float av = 0.f;
        if (p < NP) {
            int j0 = 2 * p;
            int j1 = j0 + 1;
            float4 a0 = __ldcs(&t4[j0]);
            float4 b0 = __ldcs(&d4[j0]);
            float4 a1, b1;
            bool has1 = (j1 < V4);
            if (has1) { a1 = __ldcs(&t4[j1]); b1 = __ldcs(&d4[j1]); }
            av = maxdiff4(a0, b0);
            if (has1) av += maxdiff4(a1, b1);
            s_part[pf(p)] = av;
        }
    }
    for (int p = n_iter * THREADS + tid - ((NP % THREADS) ? 0 : 0); p < PARTCAP; p += THREADS)
        if (p >= NP) s_part[pf(p)] = 0.f;
    // (also zero parts in [NP, n_iter*THREADS) range)
    for (int p = NP + tid; p < min(n_iter * THREADS, PARTCAP); p += THREADS)
        s_part[pf(p)] = 0.f;

    if (tid == 0) {
        // scalar tail (V not multiple of 4; dead for V=32000)
        float ta = 0.f, tt = 0.f;
        for (int e = V4 << 2; e < V; e++) {
            float tv = t[e], dv = d[e];
            ta += fmaxf(tv - dv, 0.f);
            tt += tv;
        }
        s_tail[0] = ta; s_tail[1] = tt;
        // acceptance test for this row
        int tk = tok[row];
        float pd = d[tk];
        float pt = t[tk];
        g_accept[row] = (u_samp[row] < fminf(1.f, pt / fmaxf(pd, EPS))) ? 1 : 0;
    }
    __syncthreads();

    // ---- Phase 2a: per-warp segment totals (each warp owns 256 parts).
    {
        int base = wid * 256 + lane * 8;
        float ls = 0.f;
        #pragma unroll
        for (int k = 0; k < 8; k++) ls += s_part[pf(base + k)];
        #pragma unroll
        for (int o = 16; o > 0; o >>= 1)
            ls += __shfl_down_sync(FULLM, ls, o);
        if (lane == 0) s_seg[wid] = ls;
    }
    __syncthreads();

    // ---- Phase 2b: warp 0 resolves the inverse-CDF crossing.
    if (wid == 0) {
        const float u = u_rec[row];

        float segv = (lane < NWARP) ? s_seg[lane] : 0.f;
        float inc  = warp_incl_scan(segv, lane);
        float ptot = __shfl_sync(FULLM, inc, NWARP - 1);
        float stot = ptot + s_tail[0];

        const bool fb = !(stot > EPS);        // fallback: sample target_probs
        float T;
        if (fb) {
            // Cold path: rebuild parts from t (correctness only).
            for (int p0 = 0; p0 < PARTCAP; p0 += 32) {
                int p = p0 + lane;
                float tvv = 0.f;
                if (p < NP) {
                    int j0 = 2 * p;
                    float4 a = t4[j0];
                    tvv = a.x + a.y + a.z + a.w;
                    if (j0 + 1 < V4) {
                        float4 a1 = t4[j0 + 1];
                        tvv += a1.x + a1.y + a1.z + a1.w;
                    }
                }
                s_part[pf(p)] = tvv;
            }
            __syncwarp();
            segv = 0.f;
            if (lane < NWARP)
                for (int k = 0; k < 256; k++)
                    segv += s_part[pf(lane * 256 + k)];
            inc  = warp_incl_scan(segv, lane);
            ptot = __shfl_sync(FULLM, inc, NWARP - 1);
            T = u;                            // target already normalized
        } else {
            T = u * stot;                     // cumsum/s < u  <=>  cumsum < u*s
        }
        float excl = inc - segv;

        unsigned m = __ballot_sync(FULLM, (lane < NWARP) && (inc >= T));
        int count;
        if (m == 0) {
            // crossing beyond all parts: walk scalar tail.
            int cc = 0;
            if (lane == 0) {
                float run = ptot;
                for (int e = V4 << 2; e < V; e++) {
                    run += fb ? t[e] : fmaxf(t[e] - d[e], 0.f);
                    cc += (run < T) ? 1 : 0;
                }
            }
            count = (V4 << 2) + __shfl_sync(FULLM, cc, 0);
        } else {
            int   ws = __ffs(m) - 1;
            float pb = __shfl_sync(FULLM, excl, ws);

            // level 2: 32 lanes x 8 parts within segment ws
            int base = ws * 256 + lane * 8;
            float ls = 0.f;
            #pragma unroll
            for (int k = 0; k < 8; k++) ls += s_part[pf(base + k)];
            float inc2 = warp_incl_scan(ls, lane);
            unsigned m2 = __ballot_sync(FULLM, pb + inc2 >= T);
            int   L  = __ffs(m2) - 1;         // guaranteed to exist
            float q  = pb + __shfl_sync(FULLM, inc2 - ls, L);

            // level 3: 8 parts of lane L on lanes 0..7
            float pv = (lane < 8) ? s_part[pf(ws * 256 + L * 8 + lane)] : 0.f;
            float inc3 = warp_incl_scan(pv, lane);
            unsigned m3 = __ballot_sync(FULLM, (lane < 8) && (q + inc3 >= T));
            int   pi = __ffs(m3) - 1;         // guaranteed to exist
            int   P  = ws * 256 + L * 8 + pi;
            float r  = q + __shfl_sync(FULLM, inc3 - pv, pi);

            // level 4: resolve within the 8 elements of part P (L2-hot).
            int cin = 0;
            if (lane == 0) {
                float ev[8];
                #pragma unroll
                for (int k = 0; k < 8; k++) ev[k] = 0.f;
                int j0 = 2 * P;
                {
                    float4 a = t4[j0];
                    if (fb) { ev[0]=a.x; ev[1]=a.y; ev[2]=a.z; ev[3]=a.w; }
                    else {
                        float4 b = d4[j0];
                        ev[0]=fmaxf(a.x-b.x,0.f); ev[1]=fmaxf(a.y-b.y,0.f);
                        ev[2]=fmaxf(a.z-b.z,0.f); ev[3]=fmaxf(a.w-b.w,0.f);
                    }
                }
                if (j0 + 1 < V4) {
                    float4 a = t4[j0 + 1];
                    if (fb) { ev[4]=a.x; ev[5]=a.y; ev[6]=a.z; ev[7]=a.w; }
                    else {
                        float4 b = d4[j0 + 1];
                        ev[4]=fmaxf(a.x-b.x,0.f); ev[5]=fmaxf(a.y-b.y,0.f);
                        ev[6]=fmaxf(a.z-b.z,0.f); ev[7]=fmaxf(a.w-b.w,0.f);
                    }
                }
                float run = r;
                #pragma unroll
                for (int k = 0; k < 8; k++) {
                    run += ev[k];
                    cin += (run < T) ? 1 : 0;
                }
            }
            count = (P << 3) + __shfl_sync(FULLM, cin, 0);
        }
        if (lane == 0) g_rec[row] = min(count, V - 1);
    }

    // ---- Last-CTA finalize.
    __syncthreads();
    if (tid == 0) {
        __threadfence();
        int ticket = atomicAdd(&g_done, 1);
        s_last = (ticket == (int)gridDim.x - 1) ? 1 : 0;
        if (s_last) {
            g_done = 0;
            __threadfence();
        }
    }
    __syncthreads();
    if (s_last) {
        for (int b = tid; b < B; b += THREADS) {
            int n_acc = 0;
            for (int i = 0; i < K; i++) {
                if (g_accept[b * K + i]) n_acc++;
                else break;
            }
            bool all_acc = (n_acc == K);
            int rec_at = g_rec[b * K + min(n_acc, K - 1)];
            int fin = all_acc ? bonus[b] : rec_at;

            float* o = out + b * (K + 1);
            for (int i = 0; i <= K; i++)
                o[i] = (i < n_acc) ? (float)tok[b * K + i] : -1.0f;
            o[n_acc] = (float)fin;

            int base = B * (K + 1);
            if (base + 4 * B <= out_size) {
                out[base + b]         = (float)(n_acc + 1);
                out[base + B + b]     = (float)n_acc;
                out[base + 2 * B + b] = all_acc ? 0.0f : 1.0f;
                out[base + 3 * B + b] = all_acc ? 1.0f : 0.0f;
            }
        }
    }
}

extern "C" void kernel_launch(void* const* d_in, const int* in_sizes, int n_in,
                              void* d_out, int out_size)
{
    const int*   tok   = (const int*)d_in[0];
    const float* dp    = (const float*)d_in[n_in - 5];
    const float* tp    = (const float*)d_in[n_in - 4];
    const int*   bonus = (const int*)d_in[n_in - 3];
    const float* us    = (const float*)d_in[n_in - 2];
    const float* ur    = (const float*)d_in[n_in - 1];
    float*       out   = (float*)d_out;

    const int N = in_sizes[0];
    const int B = in_sizes[n_in - 3];
    const int V = in_sizes[n_in - 4] / N;
    const int K = N / B;

    fused_kernel<<<N, THREADS>>>(tok, dp, tp, bonus, us, ur, out,
                                 V, B, K, out_size);
}

// round 11
// speedup vs baseline: 5.6667x; 4.0000x over previous
#include <cuda_runtime.h>
#include <cuda_bf16.h>

// Rejection sampler for speculative decoding — v5: only scan needed rows.
//
// Key insight: the reference computes the recovered token for all N rows, but
// the OUTPUT only uses it at one row per batch (the first-rejected position),
// and not at all when every draft is accepted. Acceptance needs only 2 scalar
// gathers per row. So:
//   Kernel A (grid=B, 32 thr): gathers + ballot -> n_acc, writes the full
//     token/stat output block, records needed_row[b].
//   Kernel B (grid=B, 1024 thr): for batches with a rejection, streams ONLY
//     needed_row (256 KB) and resolves the inverse-CDF sample; writes 1 float.
// Traffic drops from 262 MB to <= 33.5 MB.
//
// Inputs indexed from the END of d_in:
//   d_in[0]        draft_token_ids  int32 [N]
//   d_in[n_in-5]   draft_probs      f32   [N,V]
//   d_in[n_in-4]   target_probs     f32   [N,V]
//   d_in[n_in-3]   bonus_token_ids  int32 [B,1]
//   d_in[n_in-2]   uniform_samples  f32   [N]
//   d_in[n_in-1]   uniform_recover  f32   [N]
// Output FLOAT32: out[B,K+1], num_accepted[B], accepted[B], recovered[B], bonus[B].

#define EPS      1e-10f
#define FULLM    0xFFFFFFFFu
#define THREADSB 1024
#define NWARPB   (THREADSB / 32)
#define PARTCAP  4096                  // 8-element parts; V <= 32768
#define PARTPAD  (PARTCAP + PARTCAP / 8)

__device__ int g_nacc[8192];
__device__ int g_needrow[8192];

__device__ __forceinline__ int pf(int p) { return p + (p >> 3); }

__device__ __forceinline__ float warp_incl_scan(float v, int lane) {
    #pragma unroll
    for (int o = 1; o < 32; o <<= 1) {
        float nb = __shfl_up_sync(FULLM, v, o);
        if (lane >= o) v += nb;
    }
    return v;
}

__device__ __forceinline__ float maxdiff4(float4 a, float4 b) {
    return fmaxf(a.x - b.x, 0.f) + fmaxf(a.y - b.y, 0.f)
         + fmaxf(a.z - b.z, 0.f) + fmaxf(a.w - b.w, 0.f);
}

// ---------------- Kernel A: acceptance + output skeleton ----------------
__global__ void __launch_bounds__(32)
accept_kernel(const int* __restrict__ tok,
              const float* __restrict__ dp,
              const float* __restrict__ tp,
              const int* __restrict__ bonus,
              const float* __restrict__ us,
              float* __restrict__ out,
              int V, int B, int K, int out_size)
{
    const int b    = blockIdx.x;
    const int lane = threadIdx.x;

    bool acc = false;
    if (lane < K) {
        int row = b * K + lane;
        int tk  = tok[row];
        float pd = dp[(size_t)row * V + tk];
        float pt = tp[(size_t)row * V + tk];
        acc = us[row] < fminf(1.f, pt / fmaxf(pd, EPS));
    }
    unsigned m = __ballot_sync(FULLM, acc);   // bits >= K are 0

    if (lane == 0) {
        int n_acc = __ffs(~m) - 1;            // leading-accept count, <= K
        if (n_acc > K) n_acc = K;
        bool all_acc = (n_acc == K);

        g_nacc[b]    = n_acc;
        g_needrow[b] = b * K + min(n_acc, K - 1);

        float* o = out + b * (K + 1);
        for (int i = 0; i <= K; i++)
            o[i] = (i < n_acc) ? (float)tok[b * K + i] : -1.0f;
        if (all_acc) o[n_acc] = (float)bonus[b];
        // else: kernel B overwrites o[n_acc] with the recovered token.

        int base = B * (K + 1);
        if (base + 4 * B <= out_size) {
            out[base + b]         = (float)(n_acc + 1);
            out[base + B + b]     = (float)n_acc;
            out[base + 2 * B + b] = all_acc ? 0.0f : 1.0f;
            out[base + 3 * B + b] = all_acc ? 1.0f : 0.0f;
        }
    }
}

// ---------------- Kernel B: inverse-CDF sample for needed rows ----------------
__global__ void __launch_bounds__(THREADSB)
recover_kernel(const float* __restrict__ dp,
               const float* __restrict__ tp,
               const float* __restrict__ u_rec,
               float* __restrict__ out,
               int V, int B, int K)
{
    __shared__ float s_part[PARTPAD];
    __shared__ float s_seg[NWARPB];
    __shared__ float s_tail[2];

    const int b = blockIdx.x;
    const int n_acc = g_nacc[b];
    if (n_acc == K) return;                    // bonus path: nothing to do

    const int row  = g_needrow[b];
    const int tid  = threadIdx.x;
    const int lane = tid & 31;
    const int wid  = tid >> 5;

    const float* __restrict__ d = dp + (size_t)row * V;
    const float* __restrict__ t = tp + (size_t)row * V;

    const int V4 = V >> 2;
    const int NP = (V4 + 1) >> 1;              // 8-element parts
    const int n_iter = (NP + THREADSB - 1) / THREADSB;

    const float4* __restrict__ d4 = (const float4*)d;
    const float4* __restrict__ t4 = (const float4*)t;

    // ---- Phase 1: stream the row; 4 independent LDG.128 per thread-iter.
    #pragma unroll 4
    for (int i = 0; i < n_iter; i++) {
        int p = i * THREADSB + tid;
        if (p < NP) {
            int j0 = 2 * p;
            float4 a0 = __ldcs(&t4[j0]);
            float4 b0 = __ldcs(&d4[j0]);
            float av = maxdiff4(a0, b0);
            if (j0 + 1 < V4) {
                float4 a1 = __ldcs(&t4[j0 + 1]);
                float4 b1 = __ldcs(&d4[j0 + 1]);
                av += maxdiff4(a1, b1);
            }
            s_part[pf(p)] = av;
        }
    }
    for (int p = NP + tid; p < PARTCAP; p += THREADSB)
        s_part[pf(p)] = 0.f;

    if (tid == 0) {
        float ta = 0.f, tt = 0.f;              // scalar tail (dead for V=32000)
        for (int e = V4 << 2; e < V; e++) {
            float tv = t[e], dv = d[e];
            ta += fmaxf(tv - dv, 0.f);
            tt += tv;
        }
        s_tail[0] = ta; s_tail[1] = tt;
    }
    __syncthreads();

    // ---- Phase 2a: per-warp segment totals (each warp owns 128 parts).
    {
        int base = wid * (PARTCAP / NWARPB) + lane * 4;
        float ls = s_part[pf(base)] + s_part[pf(base + 1)]
                 + s_part[pf(base + 2)] + s_part[pf(base + 3)];
        #pragma unroll
        for (int o = 16; o > 0; o >>= 1)
            ls += __shfl_down_sync(FULLM, ls, o);
        if (lane == 0) s_seg[wid] = ls;
    }
    __syncthreads();

    // ---- Phase 2b: warp 0 resolves the crossing.
    if (wid == 0) {
        const float u = u_rec[row];

        float segv = s_seg[lane];              // 32 segments
        float inc  = warp_incl_scan(segv, lane);
        float ptot = __shfl_sync(FULLM, inc, 31);
        float stot = ptot + s_tail[0];

        const bool fb = !(stot > EPS);         // fallback: sample target_probs
        float T;
        if (fb) {
            // Cold path: rebuild parts from t (correctness only).
            for (int p0 = 0; p0 < PARTCAP; p0 += 32) {
                int p = p0 + lane;
                float tvv = 0.f;
                if (p < NP) {
                    int j0 = 2 * p;
                    float4 a = t4[j0];
                    tvv = a.x + a.y + a.z + a.w;
                    if (j0 + 1 < V4) {
                        float4 a1 = t4[j0 + 1];
                        tvv += a1.x + a1.y + a1.z + a1.w;
                    }
                }
                s_part[pf(p)] = tvv;
            }
            __syncwarp();
            segv = 0.f;
            for (int k = 0; k < PARTCAP / NWARPB; k++)
                segv += s_part[pf(lane * (PARTCAP / NWARPB) + k)];
            inc  = warp_incl_scan(segv, lane);
            ptot = __shfl_sync(FULLM, inc, 31);
            T = u;
        } else {
            T = u * stot;                      // cumsum/s < u <=> cumsum < u*s
        }
        float excl = inc - segv;

        unsigned m = __ballot_sync(FULLM, inc >= T);
        int count;
        if (m == 0) {
            int cc = 0;
            if (lane == 0) {
                float run = ptot;
                for (int e = V4 << 2; e < V; e++) {
                    run += fb ? t[e] : fmaxf(t[e] - d[e], 0.f);
                    cc += (run < T) ? 1 : 0;
                }
            }
            count = (V4 << 2) + __shfl_sync(FULLM, cc, 0);
        } else {
            int   ws = __ffs(m) - 1;
            float pb = __shfl_sync(FULLM, excl, ws);

            // level 2: 128 parts of segment ws, 4 per lane
            int base = ws * (PARTCAP / NWARPB) + lane * 4;
            float ls = s_part[pf(base)] + s_part[pf(base + 1)]
                     + s_part[pf(base + 2)] + s_part[pf(base + 3)];
            float inc2 = warp_incl_scan(ls, lane);
            unsigned m2 = __ballot_sync(FULLM, pb + inc2 >= T);
            int   L = __ffs(m2) - 1;
            float q = pb + __shfl_sync(FULLM, inc2 - ls, L);

            // level 3: 4 parts of lane L on lanes 0..3
            float pv = (lane < 4) ? s_part[pf(ws * (PARTCAP / NWARPB) + L * 4 + lane)] : 0.f;
            float inc3 = warp_incl_scan(pv, lane);
            unsigned m3 = __ballot_sync(FULLM, (lane < 4) && (q + inc3 >= T));
            int   pi = __ffs(m3) - 1;
            int   P  = ws * (PARTCAP / NWARPB) + L * 4 + pi;
            float r  = q + __shfl_sync(FULLM, inc3 - pv, pi);

            // level 4: resolve within the 8 elements of part P (L2-hot).
            int cin = 0;
            if (lane == 0) {
                float ev[8];
                #pragma unroll
                for (int k = 0; k < 8; k++) ev[k] = 0.f;
                int j0 = 2 * P;
                {
                    float4 a = t4[j0];
                    if (fb) { ev[0]=a.x; ev[1]=a.y; ev[2]=a.z; ev[3]=a.w; }
                    else {
                        float4 bb = d4[j0];
                        ev[0]=fmaxf(a.x-bb.x,0.f); ev[1]=fmaxf(a.y-bb.y,0.f);
                        ev[2]=fmaxf(a.z-bb.z,0.f); ev[3]=fmaxf(a.w-bb.w,0.f);
                    }
                }
                if (j0 + 1 < V4) {
                    float4 a = t4[j0 + 1];
                    if (fb) { ev[4]=a.x; ev[5]=a.y; ev[6]=a.z; ev[7]=a.w; }
                    else {
                        float4 bb = d4[j0 + 1];
                        ev[4]=fmaxf(a.x-bb.x,0.f); ev[5]=fmaxf(a.y-bb.y,0.f);
                        ev[6]=fmaxf(a.z-bb.z,0.f); ev[7]=fmaxf(a.w-bb.w,0.f);
                    }
                }
                float run = r;
                #pragma unroll
                for (int k = 0; k < 8; k++) {
                    run += ev[k];
                    cin += (run < T) ? 1 : 0;
                }
            }
            count = (P << 3) + __shfl_sync(FULLM, cin, 0);
        }

        if (lane == 0)
            out[b * (K + 1) + n_acc] = (float)min(count, V - 1);
    }
}

extern "C" void kernel_launch(void* const* d_in, const int* in_sizes, int n_in,
                              void* d_out, int out_size)
{
    const int*   tok   = (const int*)d_in[0];
    const float* dp    = (const float*)d_in[n_in - 5];
    const float* tp    = (const float*)d_in[n_in - 4];
    const int*   bonus = (const int*)d_in[n_in - 3];
    const float* us    = (const float*)d_in[n_in - 2];
    const float* ur    = (const float*)d_in[n_in - 1];
    float*       out   = (float*)d_out;

    const int N = in_sizes[0];
    const int B = in_sizes[n_in - 3];
    const int V = in_sizes[n_in - 4] / N;
    const int K = N / B;

    accept_kernel<<<B, 32>>>(tok, dp, tp, bonus, us, out, V, B, K, out_size);
    recover_kernel<<<B, THREADSB>>>(dp, tp, ur, out, V, B, K);
}